// round 3
// baseline (speedup 1.0000x reference)
#include <cuda_runtime.h>
#include <cstdint>

// Problem constants (fixed by the dataset)
#define N_NODES 50000
#define NPAD    50048            // 391 * 128
#define N_EDGES 800000
#define D       128
#define NGRAPH  256
#define OUTF    256
#define N_TILES (NPAD / 128)     // 391

// ---------------- device scratch (no allocations allowed) ----------------
__device__ float    g_hA[(size_t)NPAD * D];
__device__ float    g_hB[(size_t)NPAD * D];
__device__ float    g_z [(size_t)NPAD * D];
__device__ int      g_counts [N_NODES];
__device__ int      g_offsets[N_NODES + 1];
__device__ int      g_cursor [N_NODES];
__device__ int      g_esrc   [N_EDGES];
__device__ float    g_gsum[NGRAPH * D];
__device__ unsigned g_gmax[NGRAPH * D];
__device__ int      g_gcnt[NGRAPH];

// ---------------- init: zero accumulators & degree counts ----------------
__global__ void zero_kernel() {
    int i = blockIdx.x * blockDim.x + threadIdx.x;
    if (i < N_NODES) g_counts[i] = 0;
    if (i < NGRAPH * D) { g_gsum[i] = 0.f; g_gmax[i] = 0u; }
    if (i < NGRAPH) g_gcnt[i] = 0;
}

// ---------------- CSR build (bucket edges by dst) ----------------
__global__ void count_kernel(const int* __restrict__ ei) {
    int e = blockIdx.x * blockDim.x + threadIdx.x;
    if (e < N_EDGES) atomicAdd(&g_counts[ei[N_EDGES + e]], 1);
}

// single-block exclusive scan over 50000 counts (chunks of 1024)
__global__ void scan_kernel() {
    __shared__ int sh[1024];
    int t = threadIdx.x;
    int carry = 0;
    for (int base = 0; base < N_NODES; base += 1024) {
        int idx = base + t;
        int v = (idx < N_NODES) ? g_counts[idx] : 0;
        sh[t] = v;
        __syncthreads();
        for (int off = 1; off < 1024; off <<= 1) {
            int y = (t >= off) ? sh[t - off] : 0;
            __syncthreads();
            sh[t] += y;
            __syncthreads();
        }
        int incl = sh[t];
        int total = sh[1023];
        int excl = carry + incl - v;
        if (idx < N_NODES) {
            g_offsets[idx] = excl;
            g_cursor[idx]  = excl;
        }
        carry += total;
        __syncthreads();
    }
    if (t == 0) g_offsets[N_NODES] = carry;
}

__global__ void fill_kernel(const int* __restrict__ ei) {
    int e = blockIdx.x * blockDim.x + threadIdx.x;
    if (e < N_EDGES) {
        int d = ei[N_EDGES + e];
        int p = atomicAdd(&g_cursor[d], 1);
        g_esrc[p] = ei[e];
    }
}

// ---------------- aggregation: z[i] = h[i] + sum_{e in CSR[i]} h[src_e] ----
// one warp per node, one float4 (4 feats) per lane; pad rows written as zero.
__global__ void agg_kernel(const float* __restrict__ xin, int sel) {
    const float* hin = (sel == 0) ? xin : ((sel == 1) ? g_hA : g_hB);
    int w    = (blockIdx.x * blockDim.x + threadIdx.x) >> 5;
    int lane = threadIdx.x & 31;
    if (w >= NPAD) return;
    float4 acc = make_float4(0.f, 0.f, 0.f, 0.f);
    if (w < N_NODES) {
        const float4* h4 = (const float4*)hin;
        acc = h4[w * 32 + lane];
        int s = g_offsets[w];
        int e = g_offsets[w + 1];
        int j = s;
        for (; j + 4 <= e; j += 4) {
            int s0 = g_esrc[j], s1 = g_esrc[j + 1], s2 = g_esrc[j + 2], s3 = g_esrc[j + 3];
            float4 v0 = h4[s0 * 32 + lane];
            float4 v1 = h4[s1 * 32 + lane];
            float4 v2 = h4[s2 * 32 + lane];
            float4 v3 = h4[s3 * 32 + lane];
            acc.x += v0.x + v1.x + v2.x + v3.x;
            acc.y += v0.y + v1.y + v2.y + v3.y;
            acc.z += v0.z + v1.z + v2.z + v3.z;
            acc.w += v0.w + v1.w + v2.w + v3.w;
        }
        for (; j < e; j++) {
            int s0 = g_esrc[j];
            float4 v0 = h4[s0 * 32 + lane];
            acc.x += v0.x; acc.y += v0.y; acc.z += v0.z; acc.w += v0.w;
        }
    }
    ((float4*)g_z)[w * 32 + lane] = acc;
}

// ---------------- fused MLP: hout = relu( relu(z @ W1) @ W2 ) ----------------
// 128-row tile per block, full D=128 in SMEM, 8x8 register tiles, 256 threads.
// SMEM: As (A^T, k-major, [128][132] padded) + Bs ([128][128]) = 133120 B.
__global__ __launch_bounds__(256, 1)
void mlp_kernel(const float* __restrict__ w1, const float* __restrict__ w2, int outsel) {
    extern __shared__ float sm[];
    float* As = sm;                 // [128][132], As[k*132 + m] = A[m][k]
    float* Bs = sm + 128 * 132;     // [128][128], Bs[k*128 + n] = W[k][n]
    float* hout = (outsel == 1) ? g_hA : g_hB;

    const int tid = threadIdx.x;
    const int tx = tid & 15;        // output col group
    const int ty = tid >> 4;        // output row group
    const int row0 = blockIdx.x * 128;

    // Bs <- W1 (row-major [k][n], already k-major)
    {
        const float4* w4 = (const float4*)w1;
        float4* b4 = (float4*)Bs;
#pragma unroll
        for (int i = 0; i < 16; i++) b4[i * 256 + tid] = w4[i * 256 + tid];
    }
    // As <- z tile, transposed
    {
        const float4* z4 = (const float4*)(g_z + (size_t)row0 * D);
        int k4 = tid & 31;
        int mb = tid >> 5;
#pragma unroll
        for (int i = 0; i < 16; i++) {
            int m = mb + i * 8;
            float4 v = z4[m * 32 + k4];
            int k = k4 << 2;
            As[(k + 0) * 132 + m] = v.x;
            As[(k + 1) * 132 + m] = v.y;
            As[(k + 2) * 132 + m] = v.z;
            As[(k + 3) * 132 + m] = v.w;
        }
    }
    __syncthreads();

    float acc[8][8];
#pragma unroll
    for (int i = 0; i < 8; i++)
#pragma unroll
        for (int j = 0; j < 8; j++) acc[i][j] = 0.f;

#pragma unroll 4
    for (int k = 0; k < 128; k++) {
        float a[8], b[8];
        *(float4*)&a[0] = *(const float4*)&As[k * 132 + ty * 8];
        *(float4*)&a[4] = *(const float4*)&As[k * 132 + ty * 8 + 4];
        *(float4*)&b[0] = *(const float4*)&Bs[k * 128 + tx * 8];
        *(float4*)&b[4] = *(const float4*)&Bs[k * 128 + tx * 8 + 4];
#pragma unroll
        for (int i = 0; i < 8; i++)
#pragma unroll
            for (int j = 0; j < 8; j++) acc[i][j] = fmaf(a[i], b[j], acc[i][j]);
    }
    __syncthreads();

    // As <- relu(t) transposed (t[m][n] -> As[n][m]); Bs <- W2
#pragma unroll
    for (int i = 0; i < 8; i++)
#pragma unroll
        for (int j = 0; j < 8; j++)
            As[(tx * 8 + j) * 132 + (ty * 8 + i)] = fmaxf(acc[i][j], 0.f);
    {
        const float4* w4 = (const float4*)w2;
        float4* b4 = (float4*)Bs;
#pragma unroll
        for (int i = 0; i < 16; i++) b4[i * 256 + tid] = w4[i * 256 + tid];
    }
    __syncthreads();

#pragma unroll
    for (int i = 0; i < 8; i++)
#pragma unroll
        for (int j = 0; j < 8; j++) acc[i][j] = 0.f;

#pragma unroll 4
    for (int k = 0; k < 128; k++) {
        float a[8], b[8];
        *(float4*)&a[0] = *(const float4*)&As[k * 132 + ty * 8];
        *(float4*)&a[4] = *(const float4*)&As[k * 132 + ty * 8 + 4];
        *(float4*)&b[0] = *(const float4*)&Bs[k * 128 + tx * 8];
        *(float4*)&b[4] = *(const float4*)&Bs[k * 128 + tx * 8 + 4];
#pragma unroll
        for (int i = 0; i < 8; i++)
#pragma unroll
            for (int j = 0; j < 8; j++) acc[i][j] = fmaf(a[i], b[j], acc[i][j]);
    }

    // store relu(result)
#pragma unroll
    for (int i = 0; i < 8; i++) {
        int r = row0 + ty * 8 + i;
        float4 o0, o1;
        o0.x = fmaxf(acc[i][0], 0.f); o0.y = fmaxf(acc[i][1], 0.f);
        o0.z = fmaxf(acc[i][2], 0.f); o0.w = fmaxf(acc[i][3], 0.f);
        o1.x = fmaxf(acc[i][4], 0.f); o1.y = fmaxf(acc[i][5], 0.f);
        o1.z = fmaxf(acc[i][6], 0.f); o1.w = fmaxf(acc[i][7], 0.f);
        *(float4*)&hout[(size_t)r * D + tx * 8]     = o0;
        *(float4*)&hout[(size_t)r * D + tx * 8 + 4] = o1;
    }
}

// ---------------- pooling: segment sum / max / count over g_hA ----------------
__global__ void pool_kernel(const int* __restrict__ batch) {
    int i = blockIdx.x * blockDim.x + threadIdx.x;
    if (i >= N_NODES * D) return;
    int node = i >> 7;
    int f = i & 127;
    int g = batch[node];
    float v = g_hA[i];
    atomicAdd(&g_gsum[g * D + f], v);
    atomicMax(&g_gmax[g * D + f], __float_as_uint(v));  // v >= 0 post-relu
    if (f == 0) atomicAdd(&g_gcnt[g], 1);
}

// ---------------- readout: [gmax | gmean | gsum] @ out_w + out_b ----------------
__global__ void readout_kernel(const float* __restrict__ ow,
                               const float* __restrict__ ob,
                               float* __restrict__ out) {
    __shared__ float p[3 * D];
    int g = blockIdx.x;
    int o = threadIdx.x;
    if (o < D) {
        float s = g_gsum[g * D + o];
        float c = fmaxf((float)g_gcnt[g], 1.f);
        p[o]         = __uint_as_float(g_gmax[g * D + o]);
        p[D + o]     = s / c;
        p[2 * D + o] = s;
    }
    __syncthreads();
    float acc = ob[o];
#pragma unroll 8
    for (int f = 0; f < 3 * D; f++) acc = fmaf(p[f], ow[f * OUTF + o], acc);
    out[g * OUTF + o] = acc;
}

// ---------------- launch ----------------
extern "C" void kernel_launch(void* const* d_in, const int* in_sizes, int n_in,
                              void* d_out, int out_size) {
    const float* x      = (const float*)d_in[0];
    const int*   ei     = (const int*)  d_in[1];
    const int*   batch  = (const int*)  d_in[2];
    const float* w1_0   = (const float*)d_in[3];
    const float* w2_0   = (const float*)d_in[4];
    const float* gin_w1 = (const float*)d_in[5];   // [2][128][128]
    const float* gin_w2 = (const float*)d_in[6];
    const float* out_w  = (const float*)d_in[7];   // [384][256]
    const float* out_b  = (const float*)d_in[8];
    float* out = (float*)d_out;

    const int SMEM_MLP = (128 * 132 + 128 * 128) * 4;  // 133120 B
    static bool attr_done = false;
    // idempotent, device-wide; applied on first (uncaptured) correctness call
    cudaFuncSetAttribute(mlp_kernel, cudaFuncAttributeMaxDynamicSharedMemorySize, SMEM_MLP);
    (void)attr_done;

    // init + CSR build
    zero_kernel<<<(N_NODES + 255) / 256, 256>>>();
    count_kernel<<<(N_EDGES + 255) / 256, 256>>>(ei);
    scan_kernel<<<1, 1024>>>();
    fill_kernel<<<(N_EDGES + 255) / 256, 256>>>(ei);

    const int AGG_BLOCKS = NPAD / 8;  // 256 thr = 8 warps/block, 1 warp/node

    // layer 0: x -> hA
    agg_kernel<<<AGG_BLOCKS, 256>>>(x, 0);
    mlp_kernel<<<N_TILES, 256, SMEM_MLP>>>(w1_0, w2_0, 1);
    // layer 1: hA -> hB
    agg_kernel<<<AGG_BLOCKS, 256>>>(x, 1);
    mlp_kernel<<<N_TILES, 256, SMEM_MLP>>>(gin_w1, gin_w2, 2);
    // layer 2: hB -> hA
    agg_kernel<<<AGG_BLOCKS, 256>>>(x, 2);
    mlp_kernel<<<N_TILES, 256, SMEM_MLP>>>(gin_w1 + 128 * 128, gin_w2 + 128 * 128, 1);

    // pooling + readout
    pool_kernel<<<(N_NODES * D + 255) / 256, 256>>>(batch);
    readout_kernel<<<NGRAPH, 256>>>(out_w, out_b, out);
}